// round 13
// baseline (speedup 1.0000x reference)
#include <cuda_runtime.h>
#include <cuda_bf16.h>
#include <cuda_fp16.h>
#include <math.h>
#include <stdint.h>

// Problem constants
#define BATCH   4
#define SEQ     2048
#define DMODEL  1024
#define NHEADS  16
#define DHEAD   64
#define MROWS   (BATCH * SEQ)            // 8192
#define NB_ELEM ((size_t)MROWS * DMODEL)

#define LOSC 1024.0f                     // lo-part scale (avoids fp16 denormals)
#define ILOSC (1.0f / 1024.0f)

// fp16 pipeline buffers
__device__ __half g_qh[MROWS * DMODEL];       // Q post-rope, fp16
__device__ __half g_kh[MROWS * DMODEL];       // K post-rope, fp16
__device__ __half g_vh[MROWS * DMODEL];       // V, fp16
__device__ __half g_xh[MROWS * DMODEL];
__device__ __half g_xl[MROWS * DMODEL];
__device__ __half g_oh[MROWS * DMODEL];       // attention out hi
__device__ __half g_ol[MROWS * DMODEL];       // attention out lo (scaled)
__device__ __half g_wht[4][DMODEL * DMODEL];  // weights transposed [n][k]
__device__ __half g_wlt[4][DMODEL * DMODEL];

// ---------------------------------------------------------------------------
// Helpers
// ---------------------------------------------------------------------------
__device__ __forceinline__ uint32_t smem_u32(const void* p) {
    uint32_t a;
    asm("{ .reg .u64 t; cvta.to.shared.u64 t, %1; cvt.u32.u64 %0, t; }" : "=r"(a) : "l"(p));
    return a;
}
__device__ __forceinline__ void split_f16(float x, __half& h, __half& l) {
    h = __float2half_rn(x);
    l = __float2half_rn((x - __half2float(h)) * LOSC);
}
__device__ __forceinline__ uint32_t packh2h(__half a, __half b) {
    __half2 t = __halves2half2(a, b);
    return *reinterpret_cast<uint32_t*>(&t);
}
__device__ __forceinline__ uint32_t packh2(float a, float b) {
    __half2 t = __floats2half2_rn(a, b);
    return *reinterpret_cast<uint32_t*>(&t);
}
__device__ __forceinline__ void mma_f16(float* c, const uint32_t* a, const uint32_t* b) {
    asm("mma.sync.aligned.m16n8k16.row.col.f32.f16.f16.f32 "
        "{%0,%1,%2,%3}, {%4,%5,%6,%7}, {%8,%9}, {%0,%1,%2,%3};"
        : "+f"(c[0]), "+f"(c[1]), "+f"(c[2]), "+f"(c[3])
        : "r"(a[0]), "r"(a[1]), "r"(a[2]), "r"(a[3]), "r"(b[0]), "r"(b[1]));
}
__device__ __forceinline__ void mma_f16h(uint32_t* c, const uint32_t* a, const uint32_t* b) {
    asm("mma.sync.aligned.m16n8k16.row.col.f16.f16.f16.f16 "
        "{%0,%1}, {%2,%3,%4,%5}, {%6,%7}, {%0,%1};"
        : "+r"(c[0]), "+r"(c[1])
        : "r"(a[0]), "r"(a[1]), "r"(a[2]), "r"(a[3]), "r"(b[0]), "r"(b[1]));
}
__device__ __forceinline__ void ldsm4(uint32_t* r, uint32_t addr) {
    asm volatile("ldmatrix.sync.aligned.m8n8.x4.shared.b16 {%0,%1,%2,%3}, [%4];"
                 : "=r"(r[0]), "=r"(r[1]), "=r"(r[2]), "=r"(r[3]) : "r"(addr));
}
__device__ __forceinline__ void cp16(uint32_t dst, const void* src) {
    asm volatile("cp.async.cg.shared.global [%0], [%1], 16;" :: "r"(dst), "l"(src));
}
__device__ __forceinline__ void cp_commit() {
    asm volatile("cp.async.commit_group;");
}

// ---------------------------------------------------------------------------
// Split fp32 -> fp16 hi/lo
// ---------------------------------------------------------------------------
__global__ void split_plain(const float* __restrict__ X,
                            __half* __restrict__ H,
                            __half* __restrict__ L, int n4) {
    int i = blockIdx.x * blockDim.x + threadIdx.x;
    if (i >= n4) return;
    float4 v = ((const float4*)X)[i];
    __half h0,h1,h2,h3,l0,l1,l2,l3;
    split_f16(v.x, h0, l0); split_f16(v.y, h1, l1);
    split_f16(v.z, h2, l2); split_f16(v.w, h3, l3);
    ((uint2*)H)[i] = make_uint2(packh2h(h0,h1), packh2h(h2,h3));
    ((uint2*)L)[i] = make_uint2(packh2h(l0,l1), packh2h(l2,l3));
}

// ---------------------------------------------------------------------------
// Split + transpose all 4 weights in one launch (blockIdx.z selects weight).
// W[k][n] (1024x1024) -> Ht[n][k], Lt[n][k]
// ---------------------------------------------------------------------------
__global__ void split_wt4(const float* __restrict__ W0, const float* __restrict__ W1,
                          const float* __restrict__ W2, const float* __restrict__ W3,
                          __half* __restrict__ Ht, __half* __restrict__ Lt) {
    __shared__ float t[32][33];
    const int w = blockIdx.z;
    const float* W = (w == 0) ? W0 : (w == 1) ? W1 : (w == 2) ? W2 : W3;
    const size_t WSZ = (size_t)DMODEL * DMODEL;
    __half* Hw = Ht + w * WSZ;
    __half* Lw = Lt + w * WSZ;

    const int n0 = blockIdx.x * 32, k0 = blockIdx.y * 32;
    const int tx = threadIdx.x, ty = threadIdx.y;
    #pragma unroll
    for (int i = 0; i < 4; i++)
        t[ty + 8 * i][tx] = W[(size_t)(k0 + ty + 8 * i) * DMODEL + n0 + tx];
    __syncthreads();
    #pragma unroll
    for (int i = 0; i < 4; i++) {
        float v = t[tx][ty + 8 * i];
        __half h, l;
        split_f16(v, h, l);
        size_t o = (size_t)(n0 + ty + 8 * i) * DMODEL + k0 + tx;
        Hw[o] = h;
        Lw[o] = l;
    }
}

// ---------------------------------------------------------------------------
// fp16x2.5-split tensor-core GEMM, cp.async 2-stage pipeline, 2 CTAs/SM.
// mode 0: C_f32 = A*B  (final output projection)
// mode 1: fused QKV — N=3072; epilogue applies NeoX RoPE to Q,K and writes
//         fp16 to Qh/Kh/Vh (buffer = col0>>10).
// ---------------------------------------------------------------------------
#define RS   48
#define TSZ  (128 * RS * 2)          // 12288 bytes
#define SSTG (4 * TSZ)               // 49152
#define NSTG 2
#define GSMEM (NSTG * SSTG)          // 98304 -> 2 CTAs/SM

__global__ __launch_bounds__(256)
void gemm_f16s(const __half* __restrict__ AH, const __half* __restrict__ AL,
               const __half* __restrict__ BHt, const __half* __restrict__ BLt,
               float* __restrict__ C, __half* __restrict__ QH,
               __half* __restrict__ KH, __half* __restrict__ VH,
               const int* __restrict__ positions,
               int M, int N, int K, int mode) {
    extern __shared__ char smem[];
    const uint32_t sb = smem_u32(smem);

    const int tid  = threadIdx.x;
    const int lane = tid & 31;
    const int wid  = tid >> 5;
    const int wm   = wid & 3;
    const int wn   = wid >> 2;
    const int g    = lane >> 2;
    const int tg   = lane & 3;
    const int row0 = blockIdx.y * 128;
    const int col0 = blockIdx.x * 128;

    const int am = tid >> 1;
    const int ak = (tid & 1) * 16;
    const int bn = tid & 127;
    const int bk = (tid >> 7) * 16;

    const int arow  = wm * 32 + (lane & 15);
    const int akoff = (lane >> 4) * 8;
    const int brow  = wn * 64 + (lane & 7) + ((lane >> 4) << 3);
    const int bkoff = ((lane >> 3) & 1) * 8;

    float accf[2][8][4];
    uint32_t acch[2][8][2];
    #pragma unroll
    for (int i = 0; i < 2; i++)
        #pragma unroll
        for (int j = 0; j < 8; j++) {
            #pragma unroll
            for (int q = 0; q < 4; q++) accf[i][j][q] = 0.f;
            acch[i][j][0] = 0u; acch[i][j][1] = 0u;
        }

    auto issue = [&](int it) {
        const int st = it % NSTG;
        const int kc = it * 32;
        uint32_t ahs = sb + st * SSTG +          (am * RS + ak) * 2;
        uint32_t als = ahs + TSZ;
        uint32_t bhs = sb + st * SSTG + 2 * TSZ + (bn * RS + bk) * 2;
        uint32_t bls = bhs + TSZ;
        size_t ab = (size_t)(row0 + am) * K + kc + ak;
        size_t bb = (size_t)(col0 + bn) * K + kc + bk;
        cp16(ahs,      &AH[ab]);     cp16(ahs + 16, &AH[ab + 8]);
        cp16(als,      &AL[ab]);     cp16(als + 16, &AL[ab + 8]);
        cp16(bhs,      &BHt[bb]);    cp16(bhs + 16, &BHt[bb + 8]);
        cp16(bls,      &BLt[bb]);    cp16(bls + 16, &BLt[bb + 8]);
        cp_commit();
    };

    const int iters = K / 32;
    issue(0);
    issue(1);

    for (int it = 0; it < iters; it++) {
        if (it >= iters - 2)
            asm volatile("cp.async.wait_group 0;");
        else
            asm volatile("cp.async.wait_group 1;");
        __syncthreads();

        const uint32_t base = sb + (it % NSTG) * SSTG;
        const uint32_t ahb = base;
        const uint32_t alb = base + TSZ;
        const uint32_t bhb = base + 2 * TSZ;
        const uint32_t blb = base + 3 * TSZ;

        #pragma unroll
        for (int ks = 0; ks < 32; ks += 16) {
            uint32_t fah[2][4], fal[2][4], fbh[4][4], fbl[4][4];
            #pragma unroll
            for (int mi = 0; mi < 2; mi++) {
                uint32_t off = (uint32_t)(((arow + mi * 16) * RS + ks + akoff) * 2);
                ldsm4(fah[mi], ahb + off);
                ldsm4(fal[mi], alb + off);
            }
            #pragma unroll
            for (int p = 0; p < 4; p++) {
                uint32_t off = (uint32_t)(((brow + p * 16) * RS + ks + bkoff) * 2);
                ldsm4(fbh[p], bhb + off);
                ldsm4(fbl[p], blb + off);
            }
            #pragma unroll
            for (int p = 0; p < 4; p++)
                #pragma unroll
                for (int mi = 0; mi < 2; mi++) {
                    mma_f16(accf[mi][2 * p],     fah[mi], fbh[p]);
                    mma_f16(accf[mi][2 * p + 1], fah[mi], fbh[p] + 2);
                }
            #pragma unroll
            for (int p = 0; p < 4; p++)
                #pragma unroll
                for (int mi = 0; mi < 2; mi++) {
                    mma_f16h(acch[mi][2 * p],     fah[mi], fbl[p]);
                    mma_f16h(acch[mi][2 * p + 1], fah[mi], fbl[p] + 2);
                }
            #pragma unroll
            for (int p = 0; p < 4; p++)
                #pragma unroll
                for (int mi = 0; mi < 2; mi++) {
                    mma_f16h(acch[mi][2 * p],     fal[mi], fbh[p]);
                    mma_f16h(acch[mi][2 * p + 1], fal[mi], fbh[p] + 2);
                }
        }
        __syncthreads();   // all reads of stage it%NSTG done
        if (it + 2 < iters) issue(it + 2);   // refill the just-freed stage
    }

    // Combine f32 + descaled fp16 corrections into accf
    #pragma unroll
    for (int mi = 0; mi < 2; mi++)
        #pragma unroll
        for (int ni = 0; ni < 8; ni++) {
            __half2 h0 = *reinterpret_cast<__half2*>(&acch[mi][ni][0]);
            __half2 h1 = *reinterpret_cast<__half2*>(&acch[mi][ni][1]);
            accf[mi][ni][0] += __low2float(h0)  * ILOSC;
            accf[mi][ni][1] += __high2float(h0) * ILOSC;
            accf[mi][ni][2] += __low2float(h1)  * ILOSC;
            accf[mi][ni][3] += __high2float(h1) * ILOSC;
        }

    if (mode == 0) {
        #pragma unroll
        for (int mi = 0; mi < 2; mi++)
            #pragma unroll
            for (int ni = 0; ni < 8; ni++) {
                int rg = row0 + wm * 32 + mi * 16 + g;
                int cg = col0 + wn * 64 + ni * 8 + tg * 2;
                *(float2*)&C[(size_t)rg * N + cg]       = make_float2(accf[mi][ni][0], accf[mi][ni][1]);
                *(float2*)&C[(size_t)(rg + 8) * N + cg] = make_float2(accf[mi][ni][2], accf[mi][ni][3]);
            }
        return;
    }

    // mode 1: fused QKV epilogue. buffer 0=Q,1=K,2=V; rope on Q,K.
    const int buf = col0 >> 10;
    __half* dst = (buf == 0) ? QH : (buf == 1) ? KH : VH;
    const int colb0 = (col0 & (DMODEL - 1)) + wn * 64;

    if (buf < 2) {
        #pragma unroll
        for (int mi = 0; mi < 2; mi++) {
            int rg = row0 + wm * 32 + mi * 16 + g;
            float p0 = (float)positions[rg & (SEQ - 1)];
            float p1 = (float)positions[(rg + 8) & (SEQ - 1)];
            #pragma unroll
            for (int ni = 0; ni < 4; ni++) {
                #pragma unroll
                for (int q = 0; q < 2; q++) {
                    int d = ni * 8 + tg * 2 + q;
                    float invf = exp2f((float)d * -0.4152410118609203f);
                    float c0, s0, c1, s1;
                    sincosf(p0 * invf, &s0, &c0);
                    sincosf(p1 * invf, &s1, &c1);
                    float x1 = accf[mi][ni][q],     x2 = accf[mi][ni + 4][q];
                    accf[mi][ni][q]         = x1 * c0 - x2 * s0;
                    accf[mi][ni + 4][q]     = x2 * c0 + x1 * s0;
                    float y1 = accf[mi][ni][q + 2], y2 = accf[mi][ni + 4][q + 2];
                    accf[mi][ni][q + 2]     = y1 * c1 - y2 * s1;
                    accf[mi][ni + 4][q + 2] = y2 * c1 + y1 * s1;
                }
            }
        }
    }
    #pragma unroll
    for (int mi = 0; mi < 2; mi++)
        #pragma unroll
        for (int ni = 0; ni < 8; ni++) {
            int rg = row0 + wm * 32 + mi * 16 + g;
            int cg = colb0 + ni * 8 + tg * 2;
            *(uint32_t*)&dst[(size_t)rg * DMODEL + cg] =
                packh2(accf[mi][ni][0], accf[mi][ni][1]);
            *(uint32_t*)&dst[(size_t)(rg + 8) * DMODEL + cg] =
                packh2(accf[mi][ni][2], accf[mi][ni][3]);
        }
}

// ---------------------------------------------------------------------------
// Flash attention v5: fp16 in, ldmatrix fragment loads for K and Vt,
// register softmax, hi/lo fp16 O out. BQ=128, 8 warps x m16, BK=64.
// ---------------------------------------------------------------------------
#define AST 72   // smem row stride (halves): 144B, 16B-aligned

__global__ __launch_bounds__(256, 2)
void attn5_kernel(const __half* __restrict__ Q, const __half* __restrict__ K,
                  const __half* __restrict__ V,
                  __half* __restrict__ OH, __half* __restrict__ OL) {
    __shared__ __half sh[128 * AST];
    __half* Qs = sh;
    __half* Kn = sh;                   // [key][d]
    __half* Vt = sh + 64 * AST;        // [d][key]

    const int tid  = threadIdx.x;
    const int lane = tid & 31;
    const int wid  = tid >> 5;
    const int g    = lane >> 2;
    const int tg   = lane & 3;
    const int m0   = wid * 16;

    const int br8 = (lane & 7) + ((lane >> 4) << 3);
    const int bko = ((lane >> 3) & 1) * 8;
    const uint32_t knb = smem_u32(Kn);
    const uint32_t vtb = smem_u32(Vt);

    const int bh = blockIdx.y;
    const int b  = bh >> 4;
    const int h  = bh & 15;
    const int q0 = blockIdx.x * 128;
    const size_t base = (size_t)b * SEQ * DMODEL + (size_t)h * DHEAD;

    const int qr = tid >> 3;          // 0..31
    const int d8 = (tid & 7) * 8;     // 0..56

    #pragma unroll
    for (int i = 0; i < 4; i++) {
        int r = qr + 32 * i;
        *(uint4*)&Qs[r * AST + d8] =
            *(const uint4*)&Q[base + (size_t)(q0 + r) * DMODEL + d8];
    }
    __syncthreads();

    uint32_t qa[4][4];
    #pragma unroll
    for (int kst = 0; kst < 4; kst++) {
        int ks = kst * 16 + 2 * tg;
        qa[kst][0] = *(uint32_t*)&Qs[(m0 + g) * AST + ks];
        qa[kst][1] = *(uint32_t*)&Qs[(m0 + g + 8) * AST + ks];
        qa[kst][2] = *(uint32_t*)&Qs[(m0 + g) * AST + ks + 8];
        qa[kst][3] = *(uint32_t*)&Qs[(m0 + g + 8) * AST + ks + 8];
    }

    float accO[8][4];
    #pragma unroll
    for (int i = 0; i < 8; i++)
        #pragma unroll
        for (int j = 0; j < 4; j++) accO[i][j] = 0.f;
    float mr0 = -INFINITY, mr1 = -INFINITY, lr0 = 0.f, lr1 = 0.f;

    for (int kt = 0; kt < SEQ; kt += 64) {
        __syncthreads();
        #pragma unroll
        for (int i = 0; i < 2; i++) {
            int r = qr + 32 * i;
            *(uint4*)&Kn[r * AST + d8] =
                *(const uint4*)&K[base + (size_t)(kt + r) * DMODEL + d8];
            uint4 vv = *(const uint4*)&V[base + (size_t)(kt + r) * DMODEL + d8];
            const __half* vp = (const __half*)&vv;
            #pragma unroll
            for (int j = 0; j < 8; j++)
                Vt[(d8 + j) * AST + r] = vp[j];
        }
        __syncthreads();

        float s[8][4];
        #pragma unroll
        for (int i = 0; i < 8; i++)
            #pragma unroll
            for (int j = 0; j < 4; j++) s[i][j] = 0.f;
        #pragma unroll
        for (int kst = 0; kst < 4; kst++) {
            #pragma unroll
            for (int p = 0; p < 4; p++) {
                uint32_t fk[4];
                ldsm4(fk, knb + (uint32_t)(((p * 16 + br8) * AST + kst * 16 + bko) * 2));
                mma_f16(s[2 * p],     qa[kst], fk);
                mma_f16(s[2 * p + 1], qa[kst], fk + 2);
            }
        }

        float nm0 = mr0, nm1 = mr1;
        #pragma unroll
        for (int ni = 0; ni < 8; ni++) {
            nm0 = fmaxf(nm0, fmaxf(s[ni][0], s[ni][1]));
            nm1 = fmaxf(nm1, fmaxf(s[ni][2], s[ni][3]));
        }
        nm0 = fmaxf(nm0, __shfl_xor_sync(0xffffffffu, nm0, 1));
        nm0 = fmaxf(nm0, __shfl_xor_sync(0xffffffffu, nm0, 2));
        nm1 = fmaxf(nm1, __shfl_xor_sync(0xffffffffu, nm1, 1));
        nm1 = fmaxf(nm1, __shfl_xor_sync(0xffffffffu, nm1, 2));
        float a0 = __expf(mr0 - nm0);
        float a1 = __expf(mr1 - nm1);
        float sum0 = 0.f, sum1 = 0.f;
        #pragma unroll
        for (int ni = 0; ni < 8; ni++) {
            s[ni][0] = __expf(s[ni][0] - nm0); sum0 += s[ni][0];
            s[ni][1] = __expf(s[ni][1] - nm0); sum0 += s[ni][1];
            s[ni][2] = __expf(s[ni][2] - nm1); sum1 += s[ni][2];
            s[ni][3] = __expf(s[ni][3] - nm1); sum1 += s[ni][3];
        }
        sum0 += __shfl_xor_sync(0xffffffffu, sum0, 1);
        sum0 += __shfl_xor_sync(0xffffffffu, sum0, 2);
        sum1 += __shfl_xor_sync(0xffffffffu, sum1, 1);
        sum1 += __shfl_xor_sync(0xffffffffu, sum1, 2);
        lr0 = lr0 * a0 + sum0;
        lr1 = lr1 * a1 + sum1;
        mr0 = nm0; mr1 = nm1;

        #pragma unroll
        for (int ni = 0; ni < 8; ni++) {
            accO[ni][0] *= a0; accO[ni][1] *= a0;
            accO[ni][2] *= a1; accO[ni][3] *= a1;
        }

        #pragma unroll
        for (int kst = 0; kst < 4; kst++) {
            uint32_t pf[4];
            pf[0] = packh2(s[2 * kst][0],     s[2 * kst][1]);
            pf[1] = packh2(s[2 * kst][2],     s[2 * kst][3]);
            pf[2] = packh2(s[2 * kst + 1][0], s[2 * kst + 1][1]);
            pf[3] = packh2(s[2 * kst + 1][2], s[2 * kst + 1][3]);
            #pragma unroll
            for (int p = 0; p < 4; p++) {
                uint32_t fv[4];
                ldsm4(fv, vtb + (uint32_t)(((p * 16 + br8) * AST + kst * 16 + bko) * 2));
                mma_f16(accO[2 * p],     pf, fv);
                mma_f16(accO[2 * p + 1], pf, fv + 2);
            }
        }
    }

    {
        float i0 = 1.f / lr0;
        float i1 = 1.f / lr1;
        size_t r0 = base + (size_t)(q0 + m0 + g) * DMODEL;
        size_t r1 = base + (size_t)(q0 + m0 + g + 8) * DMODEL;
        #pragma unroll
        for (int ni = 0; ni < 8; ni++) {
            int c = ni * 8 + 2 * tg;
            float v00 = accO[ni][0] * i0, v01 = accO[ni][1] * i0;
            float v10 = accO[ni][2] * i1, v11 = accO[ni][3] * i1;
            __half h00, l00, h01, l01, h10, l10, h11, l11;
            split_f16(v00, h00, l00); split_f16(v01, h01, l01);
            split_f16(v10, h10, l10); split_f16(v11, h11, l11);
            *(uint32_t*)&OH[r0 + c] = packh2h(h00, h01);
            *(uint32_t*)&OL[r0 + c] = packh2h(l00, l01);
            *(uint32_t*)&OH[r1 + c] = packh2h(h10, h11);
            *(uint32_t*)&OL[r1 + c] = packh2h(l10, l11);
        }
    }
}

// ---------------------------------------------------------------------------
// Launch
// ---------------------------------------------------------------------------
extern "C" void kernel_launch(void* const* d_in, const int* in_sizes, int n_in,
                              void* d_out, int out_size) {
    const int*   positions = (const int*)d_in[0];
    const float* X  = (const float*)d_in[1];
    const float* wq = (const float*)d_in[2];
    const float* wk = (const float*)d_in[3];
    const float* wv = (const float*)d_in[4];
    const float* wo = (const float*)d_in[5];
    float* out = (float*)d_out;

    __half *qh, *kh, *vh, *xh, *xl, *oh, *ol, *wht, *wlt;
    cudaGetSymbolAddress((void**)&qh, g_qh);
    cudaGetSymbolAddress((void**)&kh, g_kh);
    cudaGetSymbolAddress((void**)&vh, g_vh);
    cudaGetSymbolAddress((void**)&xh, g_xh);
    cudaGetSymbolAddress((void**)&xl, g_xl);
    cudaGetSymbolAddress((void**)&oh, g_oh);
    cudaGetSymbolAddress((void**)&ol, g_ol);
    cudaGetSymbolAddress((void**)&wht, g_wht);
    cudaGetSymbolAddress((void**)&wlt, g_wlt);
    const size_t WSZ = (size_t)DMODEL * DMODEL;

    int n4 = (int)(NB_ELEM / 4);
    split_plain<<<(n4 + 255) / 256, 256>>>(X, xh, xl, n4);
    dim3 wtg(DMODEL / 32, DMODEL / 32, 4), wtb(32, 8);
    split_wt4<<<wtg, wtb>>>(wq, wk, wv, wo, wht, wlt);

    cudaFuncSetAttribute(gemm_f16s, cudaFuncAttributeMaxDynamicSharedMemorySize, GSMEM);
    // Fused QKV projection (3-pass) with in-epilogue RoPE, fp16 outputs
    dim3 fgrid(3 * DMODEL / 128, MROWS / 128);   // (24, 64)
    gemm_f16s<<<fgrid, 256, GSMEM>>>(xh, xl, wht, wlt,
                                     nullptr, qh, kh, vh, positions,
                                     MROWS, 3 * DMODEL, DMODEL, 1);

    attn5_kernel<<<dim3(SEQ / 128, BATCH * NHEADS), 256>>>(qh, kh, vh, oh, ol);

    dim3 ggrid(DMODEL / 128, MROWS / 128);       // (8, 64)
    gemm_f16s<<<ggrid, 256, GSMEM>>>(oh, ol, wht + 3 * WSZ, wlt + 3 * WSZ,
                                     out, nullptr, nullptr, nullptr, nullptr,
                                     MROWS, DMODEL, DMODEL, 0);
}

// round 14
// speedup vs baseline: 1.1356x; 1.1356x over previous
#include <cuda_runtime.h>
#include <cuda_bf16.h>
#include <cuda_fp16.h>
#include <math.h>
#include <stdint.h>

// Problem constants
#define BATCH   4
#define SEQ     2048
#define DMODEL  1024
#define NHEADS  16
#define DHEAD   64
#define MROWS   (BATCH * SEQ)            // 8192
#define NB_ELEM ((size_t)MROWS * DMODEL)

#define LOSC 1024.0f                     // lo-part scale (avoids fp16 denormals)
#define ILOSC (1.0f / 1024.0f)

// fp16 pipeline buffers
__device__ __half g_qh[MROWS * DMODEL];       // Q post-rope, fp16
__device__ __half g_kh[MROWS * DMODEL];       // K post-rope, fp16
__device__ __half g_vh[MROWS * DMODEL];       // V, fp16
__device__ __half g_xh[MROWS * DMODEL];
__device__ __half g_xl[MROWS * DMODEL];
__device__ __half g_oh[MROWS * DMODEL];       // attention out hi
__device__ __half g_ol[MROWS * DMODEL];       // attention out lo (scaled)
__device__ __half g_wht[4][DMODEL * DMODEL];  // weights transposed [n][k]
__device__ __half g_wlt[4][DMODEL * DMODEL];

// ---------------------------------------------------------------------------
// Helpers
// ---------------------------------------------------------------------------
__device__ __forceinline__ uint32_t smem_u32(const void* p) {
    uint32_t a;
    asm("{ .reg .u64 t; cvta.to.shared.u64 t, %1; cvt.u32.u64 %0, t; }" : "=r"(a) : "l"(p));
    return a;
}
__device__ __forceinline__ void split_f16(float x, __half& h, __half& l) {
    h = __float2half_rn(x);
    l = __float2half_rn((x - __half2float(h)) * LOSC);
}
__device__ __forceinline__ uint32_t packh2h(__half a, __half b) {
    __half2 t = __halves2half2(a, b);
    return *reinterpret_cast<uint32_t*>(&t);
}
__device__ __forceinline__ uint32_t packh2(float a, float b) {
    __half2 t = __floats2half2_rn(a, b);
    return *reinterpret_cast<uint32_t*>(&t);
}
__device__ __forceinline__ void mma_f16(float* c, const uint32_t* a, const uint32_t* b) {
    asm("mma.sync.aligned.m16n8k16.row.col.f32.f16.f16.f32 "
        "{%0,%1,%2,%3}, {%4,%5,%6,%7}, {%8,%9}, {%0,%1,%2,%3};"
        : "+f"(c[0]), "+f"(c[1]), "+f"(c[2]), "+f"(c[3])
        : "r"(a[0]), "r"(a[1]), "r"(a[2]), "r"(a[3]), "r"(b[0]), "r"(b[1]));
}
__device__ __forceinline__ void mma_f16h(uint32_t* c, const uint32_t* a, const uint32_t* b) {
    asm("mma.sync.aligned.m16n8k16.row.col.f16.f16.f16.f16 "
        "{%0,%1}, {%2,%3,%4,%5}, {%6,%7}, {%0,%1};"
        : "+r"(c[0]), "+r"(c[1])
        : "r"(a[0]), "r"(a[1]), "r"(a[2]), "r"(a[3]), "r"(b[0]), "r"(b[1]));
}
__device__ __forceinline__ void ldsm4(uint32_t* r, uint32_t addr) {
    asm volatile("ldmatrix.sync.aligned.m8n8.x4.shared.b16 {%0,%1,%2,%3}, [%4];"
                 : "=r"(r[0]), "=r"(r[1]), "=r"(r[2]), "=r"(r[3]) : "r"(addr));
}
__device__ __forceinline__ void ldsm4t(uint32_t* r, uint32_t addr) {
    asm volatile("ldmatrix.sync.aligned.m8n8.x4.trans.shared.b16 {%0,%1,%2,%3}, [%4];"
                 : "=r"(r[0]), "=r"(r[1]), "=r"(r[2]), "=r"(r[3]) : "r"(addr));
}
__device__ __forceinline__ void cp16(uint32_t dst, const void* src) {
    asm volatile("cp.async.cg.shared.global [%0], [%1], 16;" :: "r"(dst), "l"(src));
}
__device__ __forceinline__ void cp_commit() {
    asm volatile("cp.async.commit_group;");
}

// ---------------------------------------------------------------------------
// Split fp32 -> fp16 hi/lo
// ---------------------------------------------------------------------------
__global__ void split_plain(const float* __restrict__ X,
                            __half* __restrict__ H,
                            __half* __restrict__ L, int n4) {
    int i = blockIdx.x * blockDim.x + threadIdx.x;
    if (i >= n4) return;
    float4 v = ((const float4*)X)[i];
    __half h0,h1,h2,h3,l0,l1,l2,l3;
    split_f16(v.x, h0, l0); split_f16(v.y, h1, l1);
    split_f16(v.z, h2, l2); split_f16(v.w, h3, l3);
    ((uint2*)H)[i] = make_uint2(packh2h(h0,h1), packh2h(h2,h3));
    ((uint2*)L)[i] = make_uint2(packh2h(l0,l1), packh2h(l2,l3));
}

// ---------------------------------------------------------------------------
// Split + transpose all 4 weights in one launch (blockIdx.z selects weight).
// ---------------------------------------------------------------------------
__global__ void split_wt4(const float* __restrict__ W0, const float* __restrict__ W1,
                          const float* __restrict__ W2, const float* __restrict__ W3,
                          __half* __restrict__ Ht, __half* __restrict__ Lt) {
    __shared__ float t[32][33];
    const int w = blockIdx.z;
    const float* W = (w == 0) ? W0 : (w == 1) ? W1 : (w == 2) ? W2 : W3;
    const size_t WSZ = (size_t)DMODEL * DMODEL;
    __half* Hw = Ht + w * WSZ;
    __half* Lw = Lt + w * WSZ;

    const int n0 = blockIdx.x * 32, k0 = blockIdx.y * 32;
    const int tx = threadIdx.x, ty = threadIdx.y;
    #pragma unroll
    for (int i = 0; i < 4; i++)
        t[ty + 8 * i][tx] = W[(size_t)(k0 + ty + 8 * i) * DMODEL + n0 + tx];
    __syncthreads();
    #pragma unroll
    for (int i = 0; i < 4; i++) {
        float v = t[tx][ty + 8 * i];
        __half h, l;
        split_f16(v, h, l);
        size_t o = (size_t)(n0 + ty + 8 * i) * DMODEL + k0 + tx;
        Hw[o] = h;
        Lw[o] = l;
    }
}

// ---------------------------------------------------------------------------
// fp16x2.5-split tensor-core GEMM, cp.async 3-stage pipeline (R12 version).
// mode 0: C_f32 = A*B  (final output projection)
// mode 1: fused QKV — N=3072; epilogue applies NeoX RoPE to Q,K, fp16 out.
// ---------------------------------------------------------------------------
#define RS   48
#define TSZ  (128 * RS * 2)          // 12288 bytes
#define SSTG (4 * TSZ)               // 49152
#define NSTG 3
#define GSMEM (NSTG * SSTG)          // 147456

__global__ __launch_bounds__(256)
void gemm_f16s(const __half* __restrict__ AH, const __half* __restrict__ AL,
               const __half* __restrict__ BHt, const __half* __restrict__ BLt,
               float* __restrict__ C, __half* __restrict__ QH,
               __half* __restrict__ KH, __half* __restrict__ VH,
               const int* __restrict__ positions,
               int M, int N, int K, int mode) {
    extern __shared__ char smem[];
    const uint32_t sb = smem_u32(smem);

    const int tid  = threadIdx.x;
    const int lane = tid & 31;
    const int wid  = tid >> 5;
    const int wm   = wid & 3;
    const int wn   = wid >> 2;
    const int g    = lane >> 2;
    const int tg   = lane & 3;
    const int row0 = blockIdx.y * 128;
    const int col0 = blockIdx.x * 128;

    const int am = tid >> 1;
    const int ak = (tid & 1) * 16;
    const int bn = tid & 127;
    const int bk = (tid >> 7) * 16;

    const int arow  = wm * 32 + (lane & 15);
    const int akoff = (lane >> 4) * 8;
    const int brow  = wn * 64 + (lane & 7) + ((lane >> 4) << 3);
    const int bkoff = ((lane >> 3) & 1) * 8;

    float accf[2][8][4];
    uint32_t acch[2][8][2];
    #pragma unroll
    for (int i = 0; i < 2; i++)
        #pragma unroll
        for (int j = 0; j < 8; j++) {
            #pragma unroll
            for (int q = 0; q < 4; q++) accf[i][j][q] = 0.f;
            acch[i][j][0] = 0u; acch[i][j][1] = 0u;
        }

    auto issue = [&](int it) {
        const int st = it % NSTG;
        const int kc = it * 32;
        uint32_t ahs = sb + st * SSTG +          (am * RS + ak) * 2;
        uint32_t als = ahs + TSZ;
        uint32_t bhs = sb + st * SSTG + 2 * TSZ + (bn * RS + bk) * 2;
        uint32_t bls = bhs + TSZ;
        size_t ab = (size_t)(row0 + am) * K + kc + ak;
        size_t bb = (size_t)(col0 + bn) * K + kc + bk;
        cp16(ahs,      &AH[ab]);     cp16(ahs + 16, &AH[ab + 8]);
        cp16(als,      &AL[ab]);     cp16(als + 16, &AL[ab + 8]);
        cp16(bhs,      &BHt[bb]);    cp16(bhs + 16, &BHt[bb + 8]);
        cp16(bls,      &BLt[bb]);    cp16(bls + 16, &BLt[bb + 8]);
        cp_commit();
    };

    const int iters = K / 32;
    issue(0);
    issue(1);

    for (int it = 0; it < iters; it++) {
        if (it == iters - 1)
            asm volatile("cp.async.wait_group 0;");
        else
            asm volatile("cp.async.wait_group 1;");
        __syncthreads();

        if (it + 2 < iters) issue(it + 2);

        const uint32_t base = sb + (it % NSTG) * SSTG;
        const uint32_t ahb = base;
        const uint32_t alb = base + TSZ;
        const uint32_t bhb = base + 2 * TSZ;
        const uint32_t blb = base + 3 * TSZ;

        #pragma unroll
        for (int ks = 0; ks < 32; ks += 16) {
            uint32_t fah[2][4], fal[2][4], fbh[4][4], fbl[4][4];
            #pragma unroll
            for (int mi = 0; mi < 2; mi++) {
                uint32_t off = (uint32_t)(((arow + mi * 16) * RS + ks + akoff) * 2);
                ldsm4(fah[mi], ahb + off);
                ldsm4(fal[mi], alb + off);
            }
            #pragma unroll
            for (int p = 0; p < 4; p++) {
                uint32_t off = (uint32_t)(((brow + p * 16) * RS + ks + bkoff) * 2);
                ldsm4(fbh[p], bhb + off);
                ldsm4(fbl[p], blb + off);
            }
            #pragma unroll
            for (int p = 0; p < 4; p++)
                #pragma unroll
                for (int mi = 0; mi < 2; mi++) {
                    mma_f16(accf[mi][2 * p],     fah[mi], fbh[p]);
                    mma_f16(accf[mi][2 * p + 1], fah[mi], fbh[p] + 2);
                }
            #pragma unroll
            for (int p = 0; p < 4; p++)
                #pragma unroll
                for (int mi = 0; mi < 2; mi++) {
                    mma_f16h(acch[mi][2 * p],     fah[mi], fbl[p]);
                    mma_f16h(acch[mi][2 * p + 1], fah[mi], fbl[p] + 2);
                }
            #pragma unroll
            for (int p = 0; p < 4; p++)
                #pragma unroll
                for (int mi = 0; mi < 2; mi++) {
                    mma_f16h(acch[mi][2 * p],     fal[mi], fbh[p]);
                    mma_f16h(acch[mi][2 * p + 1], fal[mi], fbh[p] + 2);
                }
        }
        __syncthreads();
    }

    // Combine f32 + descaled fp16 corrections into accf
    #pragma unroll
    for (int mi = 0; mi < 2; mi++)
        #pragma unroll
        for (int ni = 0; ni < 8; ni++) {
            __half2 h0 = *reinterpret_cast<__half2*>(&acch[mi][ni][0]);
            __half2 h1 = *reinterpret_cast<__half2*>(&acch[mi][ni][1]);
            accf[mi][ni][0] += __low2float(h0)  * ILOSC;
            accf[mi][ni][1] += __high2float(h0) * ILOSC;
            accf[mi][ni][2] += __low2float(h1)  * ILOSC;
            accf[mi][ni][3] += __high2float(h1) * ILOSC;
        }

    if (mode == 0) {
        #pragma unroll
        for (int mi = 0; mi < 2; mi++)
            #pragma unroll
            for (int ni = 0; ni < 8; ni++) {
                int rg = row0 + wm * 32 + mi * 16 + g;
                int cg = col0 + wn * 64 + ni * 8 + tg * 2;
                *(float2*)&C[(size_t)rg * N + cg]       = make_float2(accf[mi][ni][0], accf[mi][ni][1]);
                *(float2*)&C[(size_t)(rg + 8) * N + cg] = make_float2(accf[mi][ni][2], accf[mi][ni][3]);
            }
        return;
    }

    // mode 1: fused QKV epilogue. buffer 0=Q,1=K,2=V; rope on Q,K.
    const int buf = col0 >> 10;
    __half* dst = (buf == 0) ? QH : (buf == 1) ? KH : VH;
    const int colb0 = (col0 & (DMODEL - 1)) + wn * 64;

    if (buf < 2) {
        #pragma unroll
        for (int mi = 0; mi < 2; mi++) {
            int rg = row0 + wm * 32 + mi * 16 + g;
            float p0 = (float)positions[rg & (SEQ - 1)];
            float p1 = (float)positions[(rg + 8) & (SEQ - 1)];
            #pragma unroll
            for (int ni = 0; ni < 4; ni++) {
                #pragma unroll
                for (int q = 0; q < 2; q++) {
                    int d = ni * 8 + tg * 2 + q;
                    float invf = exp2f((float)d * -0.4152410118609203f);
                    float c0, s0, c1, s1;
                    sincosf(p0 * invf, &s0, &c0);
                    sincosf(p1 * invf, &s1, &c1);
                    float x1 = accf[mi][ni][q],     x2 = accf[mi][ni + 4][q];
                    accf[mi][ni][q]         = x1 * c0 - x2 * s0;
                    accf[mi][ni + 4][q]     = x2 * c0 + x1 * s0;
                    float y1 = accf[mi][ni][q + 2], y2 = accf[mi][ni + 4][q + 2];
                    accf[mi][ni][q + 2]     = y1 * c1 - y2 * s1;
                    accf[mi][ni + 4][q + 2] = y2 * c1 + y1 * s1;
                }
            }
        }
    }
    #pragma unroll
    for (int mi = 0; mi < 2; mi++)
        #pragma unroll
        for (int ni = 0; ni < 8; ni++) {
            int rg = row0 + wm * 32 + mi * 16 + g;
            int cg = colb0 + ni * 8 + tg * 2;
            *(uint32_t*)&dst[(size_t)rg * DMODEL + cg] =
                packh2(accf[mi][ni][0], accf[mi][ni][1]);
            *(uint32_t*)&dst[(size_t)(rg + 8) * DMODEL + cg] =
                packh2(accf[mi][ni][2], accf[mi][ni][3]);
        }
}

// ---------------------------------------------------------------------------
// Flash attention v6: fp16 in, K via ldmatrix, V via ldmatrix.trans (no
// scalar transpose stores). Register softmax, hi/lo fp16 O out.
// BQ=128, 8 warps x m16, BK=64.
// ---------------------------------------------------------------------------
#define AST 72   // smem row stride (halves): 144B, 16B-aligned

__global__ __launch_bounds__(256, 2)
void attn6_kernel(const __half* __restrict__ Q, const __half* __restrict__ K,
                  const __half* __restrict__ V,
                  __half* __restrict__ OH, __half* __restrict__ OL) {
    __shared__ __half sh[128 * AST];
    __half* Qs = sh;
    __half* Kn = sh;                   // [key][d]
    __half* Vs = sh + 64 * AST;        // [key][d]  (same layout as K now)

    const int tid  = threadIdx.x;
    const int lane = tid & 31;
    const int wid  = tid >> 5;
    const int g    = lane >> 2;
    const int tg   = lane & 3;
    const int m0   = wid * 16;

    // K (non-trans) B-operand addressing (verified R7 pattern)
    const int br8 = (lane & 7) + ((lane >> 4) << 3);
    const int bko = ((lane >> 3) & 1) * 8;
    // V (trans) B-operand addressing: row = key, col = d
    const int vrow = ((lane >> 3) & 1) * 8 + (lane & 7);
    const int vcol = (lane >> 4) * 8;
    const uint32_t knb = smem_u32(Kn);
    const uint32_t vsb = smem_u32(Vs);

    const int bh = blockIdx.y;
    const int b  = bh >> 4;
    const int h  = bh & 15;
    const int q0 = blockIdx.x * 128;
    const size_t base = (size_t)b * SEQ * DMODEL + (size_t)h * DHEAD;

    const int qr = tid >> 3;          // 0..31
    const int d8 = (tid & 7) * 8;     // 0..56

    // Prologue: Q tile (fp16, direct copy)
    #pragma unroll
    for (int i = 0; i < 4; i++) {
        int r = qr + 32 * i;
        *(uint4*)&Qs[r * AST + d8] =
            *(const uint4*)&Q[base + (size_t)(q0 + r) * DMODEL + d8];
    }
    __syncthreads();

    uint32_t qa[4][4];
    #pragma unroll
    for (int kst = 0; kst < 4; kst++) {
        int ks = kst * 16 + 2 * tg;
        qa[kst][0] = *(uint32_t*)&Qs[(m0 + g) * AST + ks];
        qa[kst][1] = *(uint32_t*)&Qs[(m0 + g + 8) * AST + ks];
        qa[kst][2] = *(uint32_t*)&Qs[(m0 + g) * AST + ks + 8];
        qa[kst][3] = *(uint32_t*)&Qs[(m0 + g + 8) * AST + ks + 8];
    }

    float accO[8][4];
    #pragma unroll
    for (int i = 0; i < 8; i++)
        #pragma unroll
        for (int j = 0; j < 4; j++) accO[i][j] = 0.f;
    float mr0 = -INFINITY, mr1 = -INFINITY, lr0 = 0.f, lr1 = 0.f;

    for (int kt = 0; kt < SEQ; kt += 64) {
        __syncthreads();
        // K and V both vectorized row copies [key][d]
        #pragma unroll
        for (int i = 0; i < 2; i++) {
            int r = qr + 32 * i;
            *(uint4*)&Kn[r * AST + d8] =
                *(const uint4*)&K[base + (size_t)(kt + r) * DMODEL + d8];
            *(uint4*)&Vs[r * AST + d8] =
                *(const uint4*)&V[base + (size_t)(kt + r) * DMODEL + d8];
        }
        __syncthreads();

        // S = Q K^T via non-trans ldmatrix B-fragments
        float s[8][4];
        #pragma unroll
        for (int i = 0; i < 8; i++)
            #pragma unroll
            for (int j = 0; j < 4; j++) s[i][j] = 0.f;
        #pragma unroll
        for (int kst = 0; kst < 4; kst++) {
            #pragma unroll
            for (int p = 0; p < 4; p++) {
                uint32_t fk[4];
                ldsm4(fk, knb + (uint32_t)(((p * 16 + br8) * AST + kst * 16 + bko) * 2));
                mma_f16(s[2 * p],     qa[kst], fk);
                mma_f16(s[2 * p + 1], qa[kst], fk + 2);
            }
        }

        float nm0 = mr0, nm1 = mr1;
        #pragma unroll
        for (int ni = 0; ni < 8; ni++) {
            nm0 = fmaxf(nm0, fmaxf(s[ni][0], s[ni][1]));
            nm1 = fmaxf(nm1, fmaxf(s[ni][2], s[ni][3]));
        }
        nm0 = fmaxf(nm0, __shfl_xor_sync(0xffffffffu, nm0, 1));
        nm0 = fmaxf(nm0, __shfl_xor_sync(0xffffffffu, nm0, 2));
        nm1 = fmaxf(nm1, __shfl_xor_sync(0xffffffffu, nm1, 1));
        nm1 = fmaxf(nm1, __shfl_xor_sync(0xffffffffu, nm1, 2));
        float a0 = __expf(mr0 - nm0);
        float a1 = __expf(mr1 - nm1);
        float sum0 = 0.f, sum1 = 0.f;
        #pragma unroll
        for (int ni = 0; ni < 8; ni++) {
            s[ni][0] = __expf(s[ni][0] - nm0); sum0 += s[ni][0];
            s[ni][1] = __expf(s[ni][1] - nm0); sum0 += s[ni][1];
            s[ni][2] = __expf(s[ni][2] - nm1); sum1 += s[ni][2];
            s[ni][3] = __expf(s[ni][3] - nm1); sum1 += s[ni][3];
        }
        sum0 += __shfl_xor_sync(0xffffffffu, sum0, 1);
        sum0 += __shfl_xor_sync(0xffffffffu, sum0, 2);
        sum1 += __shfl_xor_sync(0xffffffffu, sum1, 1);
        sum1 += __shfl_xor_sync(0xffffffffu, sum1, 2);
        lr0 = lr0 * a0 + sum0;
        lr1 = lr1 * a1 + sum1;
        mr0 = nm0; mr1 = nm1;

        #pragma unroll
        for (int ni = 0; ni < 8; ni++) {
            accO[ni][0] *= a0; accO[ni][1] *= a0;
            accO[ni][2] *= a1; accO[ni][3] *= a1;
        }

        // O += P V via ldmatrix.trans on V [key][d]
        // ks block = kst*16 keys; p-th d-tile pair at d = p*16
        #pragma unroll
        for (int kst = 0; kst < 4; kst++) {
            uint32_t pf[4];
            pf[0] = packh2(s[2 * kst][0],     s[2 * kst][1]);
            pf[1] = packh2(s[2 * kst][2],     s[2 * kst][3]);
            pf[2] = packh2(s[2 * kst + 1][0], s[2 * kst + 1][1]);
            pf[3] = packh2(s[2 * kst + 1][2], s[2 * kst + 1][3]);
            #pragma unroll
            for (int p = 0; p < 4; p++) {
                uint32_t fv[4];
                ldsm4t(fv, vsb + (uint32_t)(((kst * 16 + vrow) * AST + p * 16 + vcol) * 2));
                mma_f16(accO[2 * p],     pf, fv);
                mma_f16(accO[2 * p + 1], pf, fv + 2);
            }
        }
    }

    // Epilogue: normalize, split hi/lo fp16, store
    {
        float i0 = 1.f / lr0;
        float i1 = 1.f / lr1;
        size_t r0 = base + (size_t)(q0 + m0 + g) * DMODEL;
        size_t r1 = base + (size_t)(q0 + m0 + g + 8) * DMODEL;
        #pragma unroll
        for (int ni = 0; ni < 8; ni++) {
            int c = ni * 8 + 2 * tg;
            float v00 = accO[ni][0] * i0, v01 = accO[ni][1] * i0;
            float v10 = accO[ni][2] * i1, v11 = accO[ni][3] * i1;
            __half h00, l00, h01, l01, h10, l10, h11, l11;
            split_f16(v00, h00, l00); split_f16(v01, h01, l01);
            split_f16(v10, h10, l10); split_f16(v11, h11, l11);
            *(uint32_t*)&OH[r0 + c] = packh2h(h00, h01);
            *(uint32_t*)&OL[r0 + c] = packh2h(l00, l01);
            *(uint32_t*)&OH[r1 + c] = packh2h(h10, h11);
            *(uint32_t*)&OL[r1 + c] = packh2h(l10, l11);
        }
    }
}

// ---------------------------------------------------------------------------
// Launch
// ---------------------------------------------------------------------------
extern "C" void kernel_launch(void* const* d_in, const int* in_sizes, int n_in,
                              void* d_out, int out_size) {
    const int*   positions = (const int*)d_in[0];
    const float* X  = (const float*)d_in[1];
    const float* wq = (const float*)d_in[2];
    const float* wk = (const float*)d_in[3];
    const float* wv = (const float*)d_in[4];
    const float* wo = (const float*)d_in[5];
    float* out = (float*)d_out;

    __half *qh, *kh, *vh, *xh, *xl, *oh, *ol, *wht, *wlt;
    cudaGetSymbolAddress((void**)&qh, g_qh);
    cudaGetSymbolAddress((void**)&kh, g_kh);
    cudaGetSymbolAddress((void**)&vh, g_vh);
    cudaGetSymbolAddress((void**)&xh, g_xh);
    cudaGetSymbolAddress((void**)&xl, g_xl);
    cudaGetSymbolAddress((void**)&oh, g_oh);
    cudaGetSymbolAddress((void**)&ol, g_ol);
    cudaGetSymbolAddress((void**)&wht, g_wht);
    cudaGetSymbolAddress((void**)&wlt, g_wlt);
    const size_t WSZ = (size_t)DMODEL * DMODEL;

    int n4 = (int)(NB_ELEM / 4);
    split_plain<<<(n4 + 255) / 256, 256>>>(X, xh, xl, n4);
    dim3 wtg(DMODEL / 32, DMODEL / 32, 4), wtb(32, 8);
    split_wt4<<<wtg, wtb>>>(wq, wk, wv, wo, wht, wlt);

    cudaFuncSetAttribute(gemm_f16s, cudaFuncAttributeMaxDynamicSharedMemorySize, GSMEM);
    // Fused QKV projection (3-pass) with in-epilogue RoPE, fp16 outputs
    dim3 fgrid(3 * DMODEL / 128, MROWS / 128);   // (24, 64)
    gemm_f16s<<<fgrid, 256, GSMEM>>>(xh, xl, wht, wlt,
                                     nullptr, qh, kh, vh, positions,
                                     MROWS, 3 * DMODEL, DMODEL, 1);

    attn6_kernel<<<dim3(SEQ / 128, BATCH * NHEADS), 256>>>(qh, kh, vh, oh, ol);

    dim3 ggrid(DMODEL / 128, MROWS / 128);       // (8, 64)
    gemm_f16s<<<ggrid, 256, GSMEM>>>(oh, ol, wht + 3 * WSZ, wlt + 3 * WSZ,
                                     out, nullptr, nullptr, nullptr, nullptr,
                                     MROWS, DMODEL, DMODEL, 0);
}

// round 15
// speedup vs baseline: 1.2729x; 1.1209x over previous
#include <cuda_runtime.h>
#include <cuda_bf16.h>
#include <cuda_fp16.h>
#include <math.h>
#include <stdint.h>

// Problem constants
#define BATCH   4
#define SEQ     2048
#define DMODEL  1024
#define NHEADS  16
#define DHEAD   64
#define MROWS   (BATCH * SEQ)            // 8192
#define NB_ELEM ((size_t)MROWS * DMODEL)

#define LOSC 1024.0f
#define ILOSC (1.0f / 1024.0f)

// fp16 pipeline buffers
__device__ __half g_qh[MROWS * DMODEL];
__device__ __half g_kh[MROWS * DMODEL];
__device__ __half g_vh[MROWS * DMODEL];
__device__ __half g_xh[MROWS * DMODEL];
__device__ __half g_xl[MROWS * DMODEL];
__device__ __half g_oh[MROWS * DMODEL];
__device__ __half g_ol[MROWS * DMODEL];
__device__ __half g_wht[4][DMODEL * DMODEL];
__device__ __half g_wlt[4][DMODEL * DMODEL];

// ---------------------------------------------------------------------------
// Helpers
// ---------------------------------------------------------------------------
__device__ __forceinline__ uint32_t smem_u32(const void* p) {
    uint32_t a;
    asm("{ .reg .u64 t; cvta.to.shared.u64 t, %1; cvt.u32.u64 %0, t; }" : "=r"(a) : "l"(p));
    return a;
}
__device__ __forceinline__ void split_f16(float x, __half& h, __half& l) {
    h = __float2half_rn(x);
    l = __float2half_rn((x - __half2float(h)) * LOSC);
}
__device__ __forceinline__ uint32_t packh2h(__half a, __half b) {
    __half2 t = __halves2half2(a, b);
    return *reinterpret_cast<uint32_t*>(&t);
}
__device__ __forceinline__ uint32_t packh2(float a, float b) {
    __half2 t = __floats2half2_rn(a, b);
    return *reinterpret_cast<uint32_t*>(&t);
}
__device__ __forceinline__ void mma_f16(float* c, const uint32_t* a, const uint32_t* b) {
    asm("mma.sync.aligned.m16n8k16.row.col.f32.f16.f16.f32 "
        "{%0,%1,%2,%3}, {%4,%5,%6,%7}, {%8,%9}, {%0,%1,%2,%3};"
        : "+f"(c[0]), "+f"(c[1]), "+f"(c[2]), "+f"(c[3])
        : "r"(a[0]), "r"(a[1]), "r"(a[2]), "r"(a[3]), "r"(b[0]), "r"(b[1]));
}
__device__ __forceinline__ void mma_f16h(uint32_t* c, const uint32_t* a, const uint32_t* b) {
    asm("mma.sync.aligned.m16n8k16.row.col.f16.f16.f16.f16 "
        "{%0,%1}, {%2,%3,%4,%5}, {%6,%7}, {%0,%1};"
        : "+r"(c[0]), "+r"(c[1])
        : "r"(a[0]), "r"(a[1]), "r"(a[2]), "r"(a[3]), "r"(b[0]), "r"(b[1]));
}
__device__ __forceinline__ void ldsm4(uint32_t* r, uint32_t addr) {
    asm volatile("ldmatrix.sync.aligned.m8n8.x4.shared.b16 {%0,%1,%2,%3}, [%4];"
                 : "=r"(r[0]), "=r"(r[1]), "=r"(r[2]), "=r"(r[3]) : "r"(addr));
}
__device__ __forceinline__ void ldsm4t(uint32_t* r, uint32_t addr) {
    asm volatile("ldmatrix.sync.aligned.m8n8.x4.trans.shared.b16 {%0,%1,%2,%3}, [%4];"
                 : "=r"(r[0]), "=r"(r[1]), "=r"(r[2]), "=r"(r[3]) : "r"(addr));
}
__device__ __forceinline__ void cp16(uint32_t dst, const void* src) {
    asm volatile("cp.async.cg.shared.global [%0], [%1], 16;" :: "r"(dst), "l"(src));
}
__device__ __forceinline__ void cp_commit() {
    asm volatile("cp.async.commit_group;");
}

// ---------------------------------------------------------------------------
// Split fp32 -> fp16 hi/lo
// ---------------------------------------------------------------------------
__global__ void split_plain(const float* __restrict__ X,
                            __half* __restrict__ H,
                            __half* __restrict__ L, int n4) {
    int i = blockIdx.x * blockDim.x + threadIdx.x;
    if (i >= n4) return;
    float4 v = ((const float4*)X)[i];
    __half h0,h1,h2,h3,l0,l1,l2,l3;
    split_f16(v.x, h0, l0); split_f16(v.y, h1, l1);
    split_f16(v.z, h2, l2); split_f16(v.w, h3, l3);
    ((uint2*)H)[i] = make_uint2(packh2h(h0,h1), packh2h(h2,h3));
    ((uint2*)L)[i] = make_uint2(packh2h(l0,l1), packh2h(l2,l3));
}

// ---------------------------------------------------------------------------
// Split + transpose all 4 weights in one launch (blockIdx.z selects weight).
// ---------------------------------------------------------------------------
__global__ void split_wt4(const float* __restrict__ W0, const float* __restrict__ W1,
                          const float* __restrict__ W2, const float* __restrict__ W3,
                          __half* __restrict__ Ht, __half* __restrict__ Lt) {
    __shared__ float t[32][33];
    const int w = blockIdx.z;
    const float* W = (w == 0) ? W0 : (w == 1) ? W1 : (w == 2) ? W2 : W3;
    const size_t WSZ = (size_t)DMODEL * DMODEL;
    __half* Hw = Ht + w * WSZ;
    __half* Lw = Lt + w * WSZ;

    const int n0 = blockIdx.x * 32, k0 = blockIdx.y * 32;
    const int tx = threadIdx.x, ty = threadIdx.y;
    #pragma unroll
    for (int i = 0; i < 4; i++)
        t[ty + 8 * i][tx] = W[(size_t)(k0 + ty + 8 * i) * DMODEL + n0 + tx];
    __syncthreads();
    #pragma unroll
    for (int i = 0; i < 4; i++) {
        float v = t[tx][ty + 8 * i];
        __half h, l;
        split_f16(v, h, l);
        size_t o = (size_t)(n0 + ty + 8 * i) * DMODEL + k0 + tx;
        Hw[o] = h;
        Lw[o] = l;
    }
}

// ---------------------------------------------------------------------------
// fp16x2.5-split tensor-core GEMM.
// BK=16 stages, NSTG=4 (96KB) -> 2 CTAs/SM, 3-deep cp.async prefetch,
// ONE __syncthreads per iteration.
// mode 0: C_f32 = A*B  (out projection); mode 1: fused QKV + RoPE, fp16 out.
// ---------------------------------------------------------------------------
#define RS   24                      // row stride (halves): 48B, 16B-aligned
#define TSZ  (128 * RS * 2)          // 6144 bytes
#define SSTG (4 * TSZ)               // 24576
#define NSTG 4
#define GSMEM (NSTG * SSTG)          // 98304 -> 2 CTAs/SM

__global__ __launch_bounds__(256, 2)
void gemm_f16s(const __half* __restrict__ AH, const __half* __restrict__ AL,
               const __half* __restrict__ BHt, const __half* __restrict__ BLt,
               float* __restrict__ C, __half* __restrict__ QH,
               __half* __restrict__ KH, __half* __restrict__ VH,
               const int* __restrict__ positions,
               int M, int N, int K, int mode) {
    extern __shared__ char smem[];
    const uint32_t sb = smem_u32(smem);

    const int tid  = threadIdx.x;
    const int lane = tid & 31;
    const int wid  = tid >> 5;
    const int wm   = wid & 3;
    const int wn   = wid >> 2;
    const int g    = lane >> 2;
    const int tg   = lane & 3;
    const int row0 = blockIdx.y * 128;
    const int col0 = blockIdx.x * 128;

    // cp.async mapping: 128 rows x 16 halves per tile; 2 threads per row.
    const int am = tid >> 1;            // 0..127
    const int ak = (tid & 1) * 8;       // half-index 0 or 8 (16B units)

    const int arow  = wm * 32 + (lane & 15);
    const int akoff = (lane >> 4) * 8;
    const int brow  = wn * 64 + (lane & 7) + ((lane >> 4) << 3);
    const int bkoff = ((lane >> 3) & 1) * 8;

    float accf[2][8][4];
    uint32_t acch[2][8][2];
    #pragma unroll
    for (int i = 0; i < 2; i++)
        #pragma unroll
        for (int j = 0; j < 8; j++) {
            #pragma unroll
            for (int q = 0; q < 4; q++) accf[i][j][q] = 0.f;
            acch[i][j][0] = 0u; acch[i][j][1] = 0u;
        }

    auto issue = [&](int it) {
        const int st = it & (NSTG - 1);
        const int kc = it * 16;
        uint32_t ahs = sb + st * SSTG +            (am * RS + ak) * 2;
        uint32_t als = ahs + TSZ;
        uint32_t bhs = sb + st * SSTG + 2 * TSZ + (am * RS + ak) * 2;
        uint32_t bls = bhs + TSZ;
        size_t ab = (size_t)(row0 + am) * K + kc + ak;
        size_t bb = (size_t)(col0 + am) * K + kc + ak;
        cp16(ahs, &AH[ab]);
        cp16(als, &AL[ab]);
        cp16(bhs, &BHt[bb]);
        cp16(bls, &BLt[bb]);
        cp_commit();
    };

    const int iters = K / 16;
    issue(0); issue(1); issue(2);

    for (int it = 0; it < iters; it++) {
        if (it < iters - 2)
            asm volatile("cp.async.wait_group 2;");
        else if (it < iters - 1)
            asm volatile("cp.async.wait_group 1;");
        else
            asm volatile("cp.async.wait_group 0;");
        __syncthreads();   // stage it visible to all; stage (it-1) reads done

        if (it + 3 < iters) issue(it + 3);   // writes buffer (it-1)%4 — safe

        const uint32_t base = sb + (it & (NSTG - 1)) * SSTG;
        const uint32_t ahb = base;
        const uint32_t alb = base + TSZ;
        const uint32_t bhb = base + 2 * TSZ;
        const uint32_t blb = base + 3 * TSZ;

        uint32_t fah[2][4], fal[2][4], fbh[4][4], fbl[4][4];
        #pragma unroll
        for (int mi = 0; mi < 2; mi++) {
            uint32_t off = (uint32_t)(((arow + mi * 16) * RS + akoff) * 2);
            ldsm4(fah[mi], ahb + off);
            ldsm4(fal[mi], alb + off);
        }
        #pragma unroll
        for (int p = 0; p < 4; p++) {
            uint32_t off = (uint32_t)(((brow + p * 16) * RS + bkoff) * 2);
            ldsm4(fbh[p], bhb + off);
            ldsm4(fbl[p], blb + off);
        }
        #pragma unroll
        for (int p = 0; p < 4; p++)
            #pragma unroll
            for (int mi = 0; mi < 2; mi++) {
                mma_f16(accf[mi][2 * p],     fah[mi], fbh[p]);
                mma_f16(accf[mi][2 * p + 1], fah[mi], fbh[p] + 2);
            }
        #pragma unroll
        for (int p = 0; p < 4; p++)
            #pragma unroll
            for (int mi = 0; mi < 2; mi++) {
                mma_f16h(acch[mi][2 * p],     fah[mi], fbl[p]);
                mma_f16h(acch[mi][2 * p + 1], fah[mi], fbl[p] + 2);
            }
        #pragma unroll
        for (int p = 0; p < 4; p++)
            #pragma unroll
            for (int mi = 0; mi < 2; mi++) {
                mma_f16h(acch[mi][2 * p],     fal[mi], fbh[p]);
                mma_f16h(acch[mi][2 * p + 1], fal[mi], fbh[p] + 2);
            }
    }

    // Combine f32 + descaled fp16 corrections
    #pragma unroll
    for (int mi = 0; mi < 2; mi++)
        #pragma unroll
        for (int ni = 0; ni < 8; ni++) {
            __half2 h0 = *reinterpret_cast<__half2*>(&acch[mi][ni][0]);
            __half2 h1 = *reinterpret_cast<__half2*>(&acch[mi][ni][1]);
            accf[mi][ni][0] += __low2float(h0)  * ILOSC;
            accf[mi][ni][1] += __high2float(h0) * ILOSC;
            accf[mi][ni][2] += __low2float(h1)  * ILOSC;
            accf[mi][ni][3] += __high2float(h1) * ILOSC;
        }

    if (mode == 0) {
        #pragma unroll
        for (int mi = 0; mi < 2; mi++)
            #pragma unroll
            for (int ni = 0; ni < 8; ni++) {
                int rg = row0 + wm * 32 + mi * 16 + g;
                int cg = col0 + wn * 64 + ni * 8 + tg * 2;
                *(float2*)&C[(size_t)rg * N + cg]       = make_float2(accf[mi][ni][0], accf[mi][ni][1]);
                *(float2*)&C[(size_t)(rg + 8) * N + cg] = make_float2(accf[mi][ni][2], accf[mi][ni][3]);
            }
        return;
    }

    // mode 1: fused QKV epilogue. buffer 0=Q,1=K,2=V; rope on Q,K.
    const int buf = col0 >> 10;
    __half* dst = (buf == 0) ? QH : (buf == 1) ? KH : VH;
    const int colb0 = (col0 & (DMODEL - 1)) + wn * 64;

    if (buf < 2) {
        #pragma unroll
        for (int mi = 0; mi < 2; mi++) {
            int rg = row0 + wm * 32 + mi * 16 + g;
            float p0 = (float)positions[rg & (SEQ - 1)];
            float p1 = (float)positions[(rg + 8) & (SEQ - 1)];
            #pragma unroll
            for (int ni = 0; ni < 4; ni++) {
                #pragma unroll
                for (int q = 0; q < 2; q++) {
                    int d = ni * 8 + tg * 2 + q;
                    float invf = exp2f((float)d * -0.4152410118609203f);
                    float c0, s0, c1, s1;
                    sincosf(p0 * invf, &s0, &c0);
                    sincosf(p1 * invf, &s1, &c1);
                    float x1 = accf[mi][ni][q],     x2 = accf[mi][ni + 4][q];
                    accf[mi][ni][q]         = x1 * c0 - x2 * s0;
                    accf[mi][ni + 4][q]     = x2 * c0 + x1 * s0;
                    float y1 = accf[mi][ni][q + 2], y2 = accf[mi][ni + 4][q + 2];
                    accf[mi][ni][q + 2]     = y1 * c1 - y2 * s1;
                    accf[mi][ni + 4][q + 2] = y2 * c1 + y1 * s1;
                }
            }
        }
    }
    #pragma unroll
    for (int mi = 0; mi < 2; mi++)
        #pragma unroll
        for (int ni = 0; ni < 8; ni++) {
            int rg = row0 + wm * 32 + mi * 16 + g;
            int cg = colb0 + ni * 8 + tg * 2;
            *(uint32_t*)&dst[(size_t)rg * DMODEL + cg] =
                packh2(accf[mi][ni][0], accf[mi][ni][1]);
            *(uint32_t*)&dst[(size_t)(rg + 8) * DMODEL + cg] =
                packh2(accf[mi][ni][2], accf[mi][ni][3]);
        }
}

// ---------------------------------------------------------------------------
// Flash attention v6 (unchanged from R14): fp16 in, K via ldmatrix, V via
// ldmatrix.trans, register softmax, hi/lo fp16 O out. BQ=128, BK=64.
// ---------------------------------------------------------------------------
#define AST 72

__global__ __launch_bounds__(256, 2)
void attn6_kernel(const __half* __restrict__ Q, const __half* __restrict__ K,
                  const __half* __restrict__ V,
                  __half* __restrict__ OH, __half* __restrict__ OL) {
    __shared__ __half sh[128 * AST];
    __half* Qs = sh;
    __half* Kn = sh;                   // [key][d]
    __half* Vs = sh + 64 * AST;        // [key][d]

    const int tid  = threadIdx.x;
    const int lane = tid & 31;
    const int wid  = tid >> 5;
    const int g    = lane >> 2;
    const int tg   = lane & 3;
    const int m0   = wid * 16;

    const int br8 = (lane & 7) + ((lane >> 4) << 3);
    const int bko = ((lane >> 3) & 1) * 8;
    const int vrow = ((lane >> 3) & 1) * 8 + (lane & 7);
    const int vcol = (lane >> 4) * 8;
    const uint32_t knb = smem_u32(Kn);
    const uint32_t vsb = smem_u32(Vs);

    const int bh = blockIdx.y;
    const int b  = bh >> 4;
    const int h  = bh & 15;
    const int q0 = blockIdx.x * 128;
    const size_t base = (size_t)b * SEQ * DMODEL + (size_t)h * DHEAD;

    const int qr = tid >> 3;
    const int d8 = (tid & 7) * 8;

    #pragma unroll
    for (int i = 0; i < 4; i++) {
        int r = qr + 32 * i;
        *(uint4*)&Qs[r * AST + d8] =
            *(const uint4*)&Q[base + (size_t)(q0 + r) * DMODEL + d8];
    }
    __syncthreads();

    uint32_t qa[4][4];
    #pragma unroll
    for (int kst = 0; kst < 4; kst++) {
        int ks = kst * 16 + 2 * tg;
        qa[kst][0] = *(uint32_t*)&Qs[(m0 + g) * AST + ks];
        qa[kst][1] = *(uint32_t*)&Qs[(m0 + g + 8) * AST + ks];
        qa[kst][2] = *(uint32_t*)&Qs[(m0 + g) * AST + ks + 8];
        qa[kst][3] = *(uint32_t*)&Qs[(m0 + g + 8) * AST + ks + 8];
    }

    float accO[8][4];
    #pragma unroll
    for (int i = 0; i < 8; i++)
        #pragma unroll
        for (int j = 0; j < 4; j++) accO[i][j] = 0.f;
    float mr0 = -INFINITY, mr1 = -INFINITY, lr0 = 0.f, lr1 = 0.f;

    for (int kt = 0; kt < SEQ; kt += 64) {
        __syncthreads();
        #pragma unroll
        for (int i = 0; i < 2; i++) {
            int r = qr + 32 * i;
            *(uint4*)&Kn[r * AST + d8] =
                *(const uint4*)&K[base + (size_t)(kt + r) * DMODEL + d8];
            *(uint4*)&Vs[r * AST + d8] =
                *(const uint4*)&V[base + (size_t)(kt + r) * DMODEL + d8];
        }
        __syncthreads();

        float s[8][4];
        #pragma unroll
        for (int i = 0; i < 8; i++)
            #pragma unroll
            for (int j = 0; j < 4; j++) s[i][j] = 0.f;
        #pragma unroll
        for (int kst = 0; kst < 4; kst++) {
            #pragma unroll
            for (int p = 0; p < 4; p++) {
                uint32_t fk[4];
                ldsm4(fk, knb + (uint32_t)(((p * 16 + br8) * AST + kst * 16 + bko) * 2));
                mma_f16(s[2 * p],     qa[kst], fk);
                mma_f16(s[2 * p + 1], qa[kst], fk + 2);
            }
        }

        float nm0 = mr0, nm1 = mr1;
        #pragma unroll
        for (int ni = 0; ni < 8; ni++) {
            nm0 = fmaxf(nm0, fmaxf(s[ni][0], s[ni][1]));
            nm1 = fmaxf(nm1, fmaxf(s[ni][2], s[ni][3]));
        }
        nm0 = fmaxf(nm0, __shfl_xor_sync(0xffffffffu, nm0, 1));
        nm0 = fmaxf(nm0, __shfl_xor_sync(0xffffffffu, nm0, 2));
        nm1 = fmaxf(nm1, __shfl_xor_sync(0xffffffffu, nm1, 1));
        nm1 = fmaxf(nm1, __shfl_xor_sync(0xffffffffu, nm1, 2));
        float a0 = __expf(mr0 - nm0);
        float a1 = __expf(mr1 - nm1);
        float sum0 = 0.f, sum1 = 0.f;
        #pragma unroll
        for (int ni = 0; ni < 8; ni++) {
            s[ni][0] = __expf(s[ni][0] - nm0); sum0 += s[ni][0];
            s[ni][1] = __expf(s[ni][1] - nm0); sum0 += s[ni][1];
            s[ni][2] = __expf(s[ni][2] - nm1); sum1 += s[ni][2];
            s[ni][3] = __expf(s[ni][3] - nm1); sum1 += s[ni][3];
        }
        sum0 += __shfl_xor_sync(0xffffffffu, sum0, 1);
        sum0 += __shfl_xor_sync(0xffffffffu, sum0, 2);
        sum1 += __shfl_xor_sync(0xffffffffu, sum1, 1);
        sum1 += __shfl_xor_sync(0xffffffffu, sum1, 2);
        lr0 = lr0 * a0 + sum0;
        lr1 = lr1 * a1 + sum1;
        mr0 = nm0; mr1 = nm1;

        #pragma unroll
        for (int ni = 0; ni < 8; ni++) {
            accO[ni][0] *= a0; accO[ni][1] *= a0;
            accO[ni][2] *= a1; accO[ni][3] *= a1;
        }

        #pragma unroll
        for (int kst = 0; kst < 4; kst++) {
            uint32_t pf[4];
            pf[0] = packh2(s[2 * kst][0],     s[2 * kst][1]);
            pf[1] = packh2(s[2 * kst][2],     s[2 * kst][3]);
            pf[2] = packh2(s[2 * kst + 1][0], s[2 * kst + 1][1]);
            pf[3] = packh2(s[2 * kst + 1][2], s[2 * kst + 1][3]);
            #pragma unroll
            for (int p = 0; p < 4; p++) {
                uint32_t fv[4];
                ldsm4t(fv, vsb + (uint32_t)(((kst * 16 + vrow) * AST + p * 16 + vcol) * 2));
                mma_f16(accO[2 * p],     pf, fv);
                mma_f16(accO[2 * p + 1], pf, fv + 2);
            }
        }
    }

    {
        float i0 = 1.f / lr0;
        float i1 = 1.f / lr1;
        size_t r0 = base + (size_t)(q0 + m0 + g) * DMODEL;
        size_t r1 = base + (size_t)(q0 + m0 + g + 8) * DMODEL;
        #pragma unroll
        for (int ni = 0; ni < 8; ni++) {
            int c = ni * 8 + 2 * tg;
            float v00 = accO[ni][0] * i0, v01 = accO[ni][1] * i0;
            float v10 = accO[ni][2] * i1, v11 = accO[ni][3] * i1;
            __half h00, l00, h01, l01, h10, l10, h11, l11;
            split_f16(v00, h00, l00); split_f16(v01, h01, l01);
            split_f16(v10, h10, l10); split_f16(v11, h11, l11);
            *(uint32_t*)&OH[r0 + c] = packh2h(h00, h01);
            *(uint32_t*)&OL[r0 + c] = packh2h(l00, l01);
            *(uint32_t*)&OH[r1 + c] = packh2h(h10, h11);
            *(uint32_t*)&OL[r1 + c] = packh2h(l10, l11);
        }
    }
}

// ---------------------------------------------------------------------------
// Launch
// ---------------------------------------------------------------------------
extern "C" void kernel_launch(void* const* d_in, const int* in_sizes, int n_in,
                              void* d_out, int out_size) {
    const int*   positions = (const int*)d_in[0];
    const float* X  = (const float*)d_in[1];
    const float* wq = (const float*)d_in[2];
    const float* wk = (const float*)d_in[3];
    const float* wv = (const float*)d_in[4];
    const float* wo = (const float*)d_in[5];
    float* out = (float*)d_out;

    __half *qh, *kh, *vh, *xh, *xl, *oh, *ol, *wht, *wlt;
    cudaGetSymbolAddress((void**)&qh, g_qh);
    cudaGetSymbolAddress((void**)&kh, g_kh);
    cudaGetSymbolAddress((void**)&vh, g_vh);
    cudaGetSymbolAddress((void**)&xh, g_xh);
    cudaGetSymbolAddress((void**)&xl, g_xl);
    cudaGetSymbolAddress((void**)&oh, g_oh);
    cudaGetSymbolAddress((void**)&ol, g_ol);
    cudaGetSymbolAddress((void**)&wht, g_wht);
    cudaGetSymbolAddress((void**)&wlt, g_wlt);
    const size_t WSZ = (size_t)DMODEL * DMODEL;

    int n4 = (int)(NB_ELEM / 4);
    split_plain<<<(n4 + 255) / 256, 256>>>(X, xh, xl, n4);
    dim3 wtg(DMODEL / 32, DMODEL / 32, 4), wtb(32, 8);
    split_wt4<<<wtg, wtb>>>(wq, wk, wv, wo, wht, wlt);

    cudaFuncSetAttribute(gemm_f16s, cudaFuncAttributeMaxDynamicSharedMemorySize, GSMEM);
    // Fused QKV projection (3-pass) with in-epilogue RoPE, fp16 outputs
    dim3 fgrid(3 * DMODEL / 128, MROWS / 128);   // (24, 64)
    gemm_f16s<<<fgrid, 256, GSMEM>>>(xh, xl, wht, wlt,
                                     nullptr, qh, kh, vh, positions,
                                     MROWS, 3 * DMODEL, DMODEL, 1);

    attn6_kernel<<<dim3(SEQ / 128, BATCH * NHEADS), 256>>>(qh, kh, vh, oh, ol);

    dim3 ggrid(DMODEL / 128, MROWS / 128);       // (8, 64)
    gemm_f16s<<<ggrid, 256, GSMEM>>>(oh, ol, wht + 3 * WSZ, wlt + 3 * WSZ,
                                     out, nullptr, nullptr, nullptr, nullptr,
                                     MROWS, DMODEL, DMODEL, 0);
}